// round 4
// baseline (speedup 1.0000x reference)
#include <cuda_runtime.h>
#include <cstdint>

#define DIM      128
#define N_NODES  50000
#define N_EDGES  625000

// ---------------- scratch (device globals: allocation-free rule) ------------
__device__ float4 g_M[(size_t)N_NODES * (DIM / 4)];     // msg_lin(X) per node
__device__ float4 g_agg[(size_t)N_NODES * (DIM / 4)];   // scatter-add accumulator
__device__ __align__(16) float g_Wt[2][DIM * DIM];      // Wt[f*DIM+g] = W[g*DIM+f]
__device__ int    g_ei_is_i64;                          // edge_index dtype flag

// ---------------- edge dtype detection (int32 vs int64) ---------------------
// If the buffer holds int64 values < N_NODES, every odd 32-bit word (the high
// half) is zero. If it holds int32 indices, odd words are real indices; the
// probability that 2048 sampled indices are all zero is (1/50000)^2048 ~= 0.
// Sample both the head (src region) and middle (dst region) of the buffer.
__global__ void detect_ei_kernel(const unsigned* __restrict__ p32) {
    __shared__ unsigned red[256];
    unsigned acc = 0;
    for (int i = threadIdx.x; i < 1024; i += 256) {
        acc |= p32[2 * i + 1];                         // head of buffer
        acc |= p32[2 * (N_EDGES / 2 + i) + 1];         // middle of buffer
    }
    red[threadIdx.x] = acc;
    __syncthreads();
    for (int s = 128; s > 0; s >>= 1) {
        if (threadIdx.x < s) red[threadIdx.x] |= red[threadIdx.x + s];
        __syncthreads();
    }
    if (threadIdx.x == 0) g_ei_is_i64 = (red[0] == 0) ? 1 : 0;
}

// ---------------- weight transpose (tiny, one-time per call) ----------------
__global__ void transpose_w_kernel(const float* __restrict__ msg_w,
                                   const float* __restrict__ lin_w) {
    int idx = blockIdx.x * blockDim.x + threadIdx.x;   // 0 .. 16383
    if (idx >= DIM * DIM) return;
    int g = idx / DIM, f = idx % DIM;
    g_Wt[0][f * DIM + g] = msg_w[idx];
    g_Wt[1][f * DIM + g] = lin_w[idx];
}

// ---------------- GEMM: out[n,g] = sum_f in[n,f] * W[g,f] + b[g] ------------
// MODE 0: in = X,                 out = g_M, also zero g_agg rows
// MODE 1: in = (1+eps)*X + g_agg, out = d_out with ReLU
// Block = 256 threads (8 warps). Each warp computes 4 rows; block = 32 rows.
template <int MODE>
__global__ void gemm_kernel(const float* __restrict__ X,
                            const float* __restrict__ bias,
                            const float* __restrict__ eps_ptr,
                            float* __restrict__ out) {
    extern __shared__ float smem[];
    float4* Wt_s = reinterpret_cast<float4*>(smem);          // DIM*DIM floats
    float*  in_s = smem + DIM * DIM;                          // 8 warps * 4 rows * DIM

    const int tid  = threadIdx.x;
    const int warp = tid >> 5;
    const int lane = tid & 31;

    const float4* Wt4 = reinterpret_cast<const float4*>(g_Wt[MODE]);
    #pragma unroll
    for (int i = 0; i < (DIM * DIM / 4) / 256; i++)
        Wt_s[tid + 256 * i] = Wt4[tid + 256 * i];

    const int row0 = blockIdx.x * 32 + warp * 4;
    float epsv = 1.0f;
    if (MODE == 1) epsv = 1.0f + *eps_ptr;

    float* my_in = in_s + warp * 4 * DIM;
    #pragma unroll
    for (int r = 0; r < 4; r++) {
        const int row = row0 + r;
        if (row < N_NODES) {
            float4 v = reinterpret_cast<const float4*>(X + (size_t)row * DIM)[lane];
            if (MODE == 1) {
                float4 a = g_agg[(size_t)row * (DIM / 4) + lane];
                v.x = fmaf(epsv, v.x, a.x);
                v.y = fmaf(epsv, v.y, a.y);
                v.z = fmaf(epsv, v.z, a.z);
                v.w = fmaf(epsv, v.w, a.w);
            }
            reinterpret_cast<float4*>(my_in + r * DIM)[lane] = v;
        }
    }
    __syncthreads();

    float acc[4][4];
    #pragma unroll
    for (int r = 0; r < 4; r++)
        #pragma unroll
        for (int c = 0; c < 4; c++) acc[r][c] = 0.0f;

    #pragma unroll 4
    for (int j = 0; j < DIM / 4; j++) {
        float4 w0 = Wt_s[(4 * j + 0) * (DIM / 4) + lane];
        float4 w1 = Wt_s[(4 * j + 1) * (DIM / 4) + lane];
        float4 w2 = Wt_s[(4 * j + 2) * (DIM / 4) + lane];
        float4 w3 = Wt_s[(4 * j + 3) * (DIM / 4) + lane];
        #pragma unroll
        for (int r = 0; r < 4; r++) {
            float4 b = reinterpret_cast<const float4*>(my_in + r * DIM)[j];
            acc[r][0] += b.x * w0.x + b.y * w1.x + b.z * w2.x + b.w * w3.x;
            acc[r][1] += b.x * w0.y + b.y * w1.y + b.z * w2.y + b.w * w3.y;
            acc[r][2] += b.x * w0.z + b.y * w1.z + b.z * w2.z + b.w * w3.z;
            acc[r][3] += b.x * w0.w + b.y * w1.w + b.z * w2.w + b.w * w3.w;
        }
    }

    const float4 bv = reinterpret_cast<const float4*>(bias)[lane];
    #pragma unroll
    for (int r = 0; r < 4; r++) {
        const int row = row0 + r;
        if (row >= N_NODES) continue;
        float4 o;
        o.x = acc[r][0] + bv.x;
        o.y = acc[r][1] + bv.y;
        o.z = acc[r][2] + bv.z;
        o.w = acc[r][3] + bv.w;
        if (MODE == 0) {
            g_M[(size_t)row * (DIM / 4) + lane] = o;
            g_agg[(size_t)row * (DIM / 4) + lane] = make_float4(0.f, 0.f, 0.f, 0.f);
        } else {
            o.x = fmaxf(o.x, 0.f);
            o.y = fmaxf(o.y, 0.f);
            o.z = fmaxf(o.z, 0.f);
            o.w = fmaxf(o.w, 0.f);
            reinterpret_cast<float4*>(out + (size_t)row * DIM)[lane] = o;
        }
    }
}

// ---------------- scatter: agg[src[e]] += M[dst[e]] -------------------------
// One warp per edge; dtype-adaptive index decode (int32 vs int64 layout).
__global__ void scatter_kernel(const void* __restrict__ ei_raw) {
    const int e = blockIdx.x * (blockDim.x >> 5) + (threadIdx.x >> 5);
    if (e >= N_EDGES) return;
    const int lane = threadIdx.x & 31;

    unsigned src, dst;
    if (g_ei_is_i64) {
        const long long* p = (const long long*)ei_raw;
        src = (unsigned)p[e];
        dst = (unsigned)p[N_EDGES + e];
    } else {
        const int* p = (const int*)ei_raw;
        src = (unsigned)p[e];
        dst = (unsigned)p[N_EDGES + e];
    }
    if (src >= N_NODES || dst >= N_NODES) return;   // defensive

    const float4 v = __ldg(&g_M[(size_t)dst * (DIM / 4) + lane]);
    float4* a = &g_agg[(size_t)src * (DIM / 4) + lane];
    asm volatile("red.global.add.v4.f32 [%0], {%1, %2, %3, %4};"
                 :: "l"(a), "f"(v.x), "f"(v.y), "f"(v.z), "f"(v.w)
                 : "memory");
}

// ---------------- launch ----------------------------------------------------
extern "C" void kernel_launch(void* const* d_in, const int* in_sizes, int n_in,
                              void* d_out, int out_size) {
    // Resolve inputs by element count (unique sizes), keep order for w/b pairs.
    const float* X   = nullptr;
    const void*  ei  = nullptr;
    const float* eps = nullptr;
    const float* w[2] = {nullptr, nullptr};   // [msg_w, lin_w]
    const float* b[2] = {nullptr, nullptr};   // [msg_b, lin_b]
    int wi = 0, bi = 0;
    for (int i = 0; i < n_in; i++) {
        const int s = in_sizes[i];
        if      (s == N_NODES * DIM) X   = (const float*)d_in[i];
        else if (s == 2 * N_EDGES)   ei  = d_in[i];
        else if (s == 1)             eps = (const float*)d_in[i];
        else if (s == DIM * DIM)   { if (wi < 2) w[wi++] = (const float*)d_in[i]; }
        else if (s == DIM)         { if (bi < 2) b[bi++] = (const float*)d_in[i]; }
    }
    float* out = (float*)d_out;

    const int smem_bytes = (DIM * DIM + 8 * 4 * DIM) * sizeof(float);  // 80KB
    cudaFuncSetAttribute(gemm_kernel<0>, cudaFuncAttributeMaxDynamicSharedMemorySize, smem_bytes);
    cudaFuncSetAttribute(gemm_kernel<1>, cudaFuncAttributeMaxDynamicSharedMemorySize, smem_bytes);

    const int gemm_blocks = (N_NODES + 31) / 32;           // 1563
    const int scat_blocks = (N_EDGES + 7) / 8;             // 78125 (8 warps/block)

    detect_ei_kernel<<<1, 256>>>((const unsigned*)ei);
    transpose_w_kernel<<<(DIM * DIM + 255) / 256, 256>>>(w[0], w[1]);
    gemm_kernel<0><<<gemm_blocks, 256, smem_bytes>>>(X, b[0], eps, nullptr);
    scatter_kernel<<<scat_blocks, 256>>>(ei);
    gemm_kernel<1><<<gemm_blocks, 256, smem_bytes>>>(X, b[1], eps, out);
}

// round 7
// speedup vs baseline: 1.1656x; 1.1656x over previous
#include <cuda_runtime.h>
#include <cuda_bf16.h>
#include <cstdint>

#define DIM      128
#define N_NODES  50000
#define N_EDGES  625000
#define TILE_M   128
#define NTILES   ((N_NODES + TILE_M - 1) / TILE_M)   // 391

// SMEM tile geometry: bf16 128x128 tiles, row stride 272B (256B data + 16B pad
// -> ldmatrix 16B accesses from 8 consecutive rows hit disjoint bank groups).
#define ASTRIDE    272
#define TILE_BYTES (128 * ASTRIDE)                    // 34816
#define SM_AHI     0
#define SM_ALO     (1 * TILE_BYTES)
#define SM_BHI     (2 * TILE_BYTES)
#define SM_BLO     (3 * TILE_BYTES)
#define SM_TOTAL   (4 * TILE_BYTES)                   // 139264 B

// ---------------- scratch (device globals) ----------------------------------
__device__ float4 g_aggX[(size_t)N_NODES * (DIM / 4)];  // sum of X[dst] per src
__device__ float  g_deg[N_NODES];                       // degree per src
__device__ int    g_ei_is_i64;

// ---------------- helpers ----------------------------------------------------
__device__ __forceinline__ uint32_t smem_u32(const void* p) {
    uint32_t a;
    asm("{ .reg .u64 t; cvta.to.shared.u64 t, %1; cvt.u32.u64 %0, t; }" : "=r"(a) : "l"(p));
    return a;
}

#define LDSM_X4(r, addr)                                                        \
    asm volatile("ldmatrix.sync.aligned.m8n8.x4.shared.b16 {%0,%1,%2,%3}, [%4];"\
                 : "=r"((r)[0]), "=r"((r)[1]), "=r"((r)[2]), "=r"((r)[3])       \
                 : "r"(addr))
#define LDSM_X2(r, addr)                                                        \
    asm volatile("ldmatrix.sync.aligned.m8n8.x2.shared.b16 {%0,%1}, [%2];"      \
                 : "=r"((r)[0]), "=r"((r)[1]) : "r"(addr))
#define MMA_BF16(c, a, b)                                                       \
    asm volatile("mma.sync.aligned.m16n8k16.row.col.f32.bf16.bf16.f32 "         \
                 "{%0,%1,%2,%3}, {%4,%5,%6,%7}, {%8,%9}, {%0,%1,%2,%3};"        \
                 : "+f"((c)[0]), "+f"((c)[1]), "+f"((c)[2]), "+f"((c)[3])       \
                 : "r"((a)[0]), "r"((a)[1]), "r"((a)[2]), "r"((a)[3]),          \
                   "r"((b)[0]), "r"((b)[1]))

// Split (a,b) -> bf16 hi pair + residual lo pair; store packed u32 to both tiles.
__device__ __forceinline__ void store_pair(char* hi_t, char* lo_t, int row, int col,
                                           float a, float b) {
    const uint32_t off = (uint32_t)row * ASTRIDE + (uint32_t)col * 2;
    __nv_bfloat162 h = __floats2bfloat162_rn(a, b);
    float ra = a - __bfloat162float(__low2bfloat16(h));
    float rb = b - __bfloat162float(__high2bfloat16(h));
    __nv_bfloat162 l = __floats2bfloat162_rn(ra, rb);
    *(uint32_t*)(hi_t + off) = *(uint32_t*)&h;
    *(uint32_t*)(lo_t + off) = *(uint32_t*)&l;
}

// ---------------- small kernels ---------------------------------------------
__global__ void detect_ei_kernel(const unsigned* __restrict__ p32) {
    __shared__ unsigned red[256];
    unsigned acc = 0;
    for (int i = threadIdx.x; i < 1024; i += 256) {
        acc |= p32[2 * i + 1];
        acc |= p32[2 * (N_EDGES / 2 + i) + 1];
    }
    red[threadIdx.x] = acc;
    __syncthreads();
    for (int s = 128; s > 0; s >>= 1) {
        if (threadIdx.x < s) red[threadIdx.x] |= red[threadIdx.x + s];
        __syncthreads();
    }
    if (threadIdx.x == 0) g_ei_is_i64 = (red[0] == 0) ? 1 : 0;
}

__global__ void zero_kernel() {
    int i = blockIdx.x * blockDim.x + threadIdx.x;
    if (i < N_NODES * (DIM / 4)) g_aggX[i] = make_float4(0.f, 0.f, 0.f, 0.f);
    if (i < N_NODES) g_deg[i] = 0.f;
}

// scatter: aggX[src] += X[dst]; deg[src] += 1. One warp per edge.
__global__ void scatter_kernel(const void* __restrict__ ei_raw,
                               const float* __restrict__ X) {
    const int e = blockIdx.x * (blockDim.x >> 5) + (threadIdx.x >> 5);
    if (e >= N_EDGES) return;
    const int lane = threadIdx.x & 31;

    unsigned src, dst;
    if (g_ei_is_i64) {
        const long long* p = (const long long*)ei_raw;
        src = (unsigned)p[e];
        dst = (unsigned)p[N_EDGES + e];
    } else {
        const int* p = (const int*)ei_raw;
        src = (unsigned)p[e];
        dst = (unsigned)p[N_EDGES + e];
    }
    if (src >= N_NODES || dst >= N_NODES) return;

    const float4 v = __ldg(reinterpret_cast<const float4*>(X) + (size_t)dst * (DIM / 4) + lane);
    float4* a = &g_aggX[(size_t)src * (DIM / 4) + lane];
    asm volatile("red.global.add.v4.f32 [%0], {%1, %2, %3, %4};"
                 :: "l"(a), "f"(v.x), "f"(v.y), "f"(v.z), "f"(v.w) : "memory");
    if (lane == 0)
        asm volatile("red.global.add.f32 [%0], %1;" :: "l"(&g_deg[src]), "f"(1.0f) : "memory");
}

// ---------------- fused double-GEMM (mma.sync bf16 hi/lo split) --------------
// Per 256-thread CTA (128 rows): warp w owns rows [16w, 16w+16).
//   y   = msg_W . aggX[row] + deg[row]*msg_b + (1+eps)*X[row]
//   out = relu(lin_W . y + lin_b)
// Each GEMM = 3 passes (Ahi.Bhi + Alo.Bhi + Ahi.Blo), fp32 accumulate.

// fill B tiles (both weight layouts are [g][f] row-major = col-major KxN: perfect)
__device__ __forceinline__ void fill_B(char* smem, const float* __restrict__ w,
                                       int tid) {
    const int row = tid >> 1;                  // weight row g = output col n
    const int c0  = (tid & 1) * 64;
    const float2* wr = (const float2*)(w + (size_t)row * DIM + c0);
    #pragma unroll 8
    for (int c = 0; c < 64; c += 2) {
        float2 v = __ldg(wr + c / 2);
        store_pair(smem + SM_BHI, smem + SM_BLO, row, c0 + c, v.x, v.y);
    }
}

__device__ __forceinline__ void do_gemm(uint32_t sb, int w, int t, float (*acc)[4]) {
    #pragma unroll 1
    for (int k = 0; k < 8; k++) {
        const uint32_t a_addr = sb + SM_AHI + (uint32_t)(w * 16 + (t & 15)) * ASTRIDE
                              + (uint32_t)k * 32 + (uint32_t)(t >> 4) * 16;
        uint32_t ah[4], al[4];
        LDSM_X4(ah, a_addr);
        LDSM_X4(al, a_addr + TILE_BYTES);
        #pragma unroll
        for (int j = 0; j < 16; j++) {
            const uint32_t b_addr = sb + SM_BHI + (uint32_t)(j * 8 + (t & 7)) * ASTRIDE
                                  + (uint32_t)k * 32 + (uint32_t)((t >> 3) & 1) * 16;
            uint32_t bh[2], bl[2];
            LDSM_X2(bh, b_addr);
            LDSM_X2(bl, b_addr + TILE_BYTES);
            MMA_BF16(acc[j], ah, bh);
            MMA_BF16(acc[j], al, bh);
            MMA_BF16(acc[j], ah, bl);
        }
    }
}

__global__ void __launch_bounds__(256, 1)
fused_kernel(const float* __restrict__ X,
             const float* __restrict__ msg_w, const float* __restrict__ msg_b,
             const float* __restrict__ lin_w, const float* __restrict__ lin_b,
             const float* __restrict__ eps_ptr, float* __restrict__ out) {
    extern __shared__ char smem[];
    const uint32_t sb = smem_u32(smem);
    const int tid = threadIdx.x;
    const int w = tid >> 5, t = tid & 31;
    const int g = t >> 2, tig = t & 3;
    const int base = blockIdx.x * TILE_M;

    // ---- fill A (aggX hi/lo) and B (msg_w hi/lo) ----
    {
        const int row = tid >> 1;
        const int c0 = (tid & 1) * 64;
        const int grow = base + row;
        const bool v = (grow < N_NODES);
        const float2* ar = (const float2*)((const float*)g_aggX + (size_t)grow * DIM + c0);
        #pragma unroll 8
        for (int c = 0; c < 64; c += 2) {
            float2 a = v ? __ldg(ar + c / 2) : make_float2(0.f, 0.f);
            store_pair(smem + SM_AHI, smem + SM_ALO, row, c0 + c, a.x, a.y);
        }
        fill_B(smem, msg_w, tid);
    }
    __syncthreads();

    float acc[16][4];
    #pragma unroll
    for (int j = 0; j < 16; j++)
        #pragma unroll
        for (int i = 0; i < 4; i++) acc[j][i] = 0.f;

    // ---- GEMM 1: acc = msg_W . aggX ----
    do_gemm(sb, w, t, acc);

    // ---- epilogue 1: y = acc + deg*msg_b + (1+eps)X -> back into A tiles ----
    const float epsv = 1.0f + __ldg(eps_ptr);
    const int r0 = w * 16 + g, r1 = r0 + 8;
    const int gr0 = base + r0, gr1 = base + r1;
    const bool v0 = (gr0 < N_NODES), v1 = (gr1 < N_NODES);
    const float d0 = v0 ? __ldg(&g_deg[gr0]) : 0.f;
    const float d1 = v1 ? __ldg(&g_deg[gr1]) : 0.f;
    #pragma unroll
    for (int j = 0; j < 16; j++) {
        const int col = j * 8 + 2 * tig;
        float2 mb = __ldg((const float2*)(msg_b + col));
        float2 x0 = v0 ? __ldg((const float2*)(X + (size_t)gr0 * DIM + col)) : make_float2(0.f, 0.f);
        float2 x1 = v1 ? __ldg((const float2*)(X + (size_t)gr1 * DIM + col)) : make_float2(0.f, 0.f);
        float y00 = acc[j][0] + d0 * mb.x + epsv * x0.x;
        float y01 = acc[j][1] + d0 * mb.y + epsv * x0.y;
        float y10 = acc[j][2] + d1 * mb.x + epsv * x1.x;
        float y11 = acc[j][3] + d1 * mb.y + epsv * x1.y;
        store_pair(smem + SM_AHI, smem + SM_ALO, r0, col, y00, y01);
        store_pair(smem + SM_AHI, smem + SM_ALO, r1, col, y10, y11);
        acc[j][0] = acc[j][1] = acc[j][2] = acc[j][3] = 0.f;
    }
    __syncthreads();                 // all warps done reading msg_w B tiles
    fill_B(smem, lin_w, tid);        // overwrite B with lin_w
    __syncthreads();

    // ---- GEMM 2: acc = lin_W . y ----
    do_gemm(sb, w, t, acc);

    // ---- epilogue 2: out = relu(acc + lin_b) ----
    #pragma unroll
    for (int j = 0; j < 16; j++) {
        const int col = j * 8 + 2 * tig;
        float2 lb = __ldg((const float2*)(lin_b + col));
        if (v0) {
            float2 o;
            o.x = fmaxf(acc[j][0] + lb.x, 0.f);
            o.y = fmaxf(acc[j][1] + lb.y, 0.f);
            *(float2*)(out + (size_t)gr0 * DIM + col) = o;
        }
        if (v1) {
            float2 o;
            o.x = fmaxf(acc[j][2] + lb.x, 0.f);
            o.y = fmaxf(acc[j][3] + lb.y, 0.f);
            *(float2*)(out + (size_t)gr1 * DIM + col) = o;
        }
    }
}

// ---------------- launch ----------------------------------------------------
extern "C" void kernel_launch(void* const* d_in, const int* in_sizes, int n_in,
                              void* d_out, int out_size) {
    const float* X   = nullptr;
    const void*  ei  = nullptr;
    const float* eps = nullptr;
    const float* w[2] = {nullptr, nullptr};   // [msg_w, lin_w]
    const float* b[2] = {nullptr, nullptr};   // [msg_b, lin_b]
    int wi = 0, bi = 0;
    for (int i = 0; i < n_in; i++) {
        const int s = in_sizes[i];
        if      (s == N_NODES * DIM) X   = (const float*)d_in[i];
        else if (s == 2 * N_EDGES)   ei  = d_in[i];
        else if (s == 1)             eps = (const float*)d_in[i];
        else if (s == DIM * DIM)   { if (wi < 2) w[wi++] = (const float*)d_in[i]; }
        else if (s == DIM)         { if (bi < 2) b[bi++] = (const float*)d_in[i]; }
    }
    float* out = (float*)d_out;

    cudaFuncSetAttribute(fused_kernel, cudaFuncAttributeMaxDynamicSharedMemorySize, SM_TOTAL);

    const int zero_blocks = (N_NODES * (DIM / 4) + 255) / 256;   // 6250
    const int scat_blocks = (N_EDGES + 7) / 8;                   // 78125

    detect_ei_kernel<<<1, 256>>>((const unsigned*)ei);
    zero_kernel<<<zero_blocks, 256>>>();
    scatter_kernel<<<scat_blocks, 256>>>(ei, X);
    fused_kernel<<<NTILES, 256, SM_TOTAL>>>(X, w[0], b[0], w[1], b[1], eps, out);
}

// round 8
// speedup vs baseline: 1.2603x; 1.0812x over previous
#include <cuda_runtime.h>
#include <cuda_fp16.h>
#include <cstdint>

#define DIM      128
#define N_NODES  50000
#define N_EDGES  625000
#define TILE_M   128
#define NTILES   ((N_NODES + TILE_M - 1) / TILE_M)   // 391

// SMEM tile geometry: fp16 128x128 tiles, row stride 272B (256B data + 16B pad
// -> ldmatrix 16B accesses from 8 consecutive rows hit disjoint bank groups).
#define ASTRIDE    272
#define TILE_BYTES (128 * ASTRIDE)                    // 34816
#define SM_AHI     0
#define SM_ALO     (1 * TILE_BYTES)
#define SM_BHI     (2 * TILE_BYTES)
#define SM_TOTAL   (3 * TILE_BYTES)                   // 104448 B

// ---------------- scratch (device globals) ----------------------------------
__device__ float4 g_aggX[(size_t)N_NODES * (DIM / 4)];  // sum of X[dst] per src
__device__ float  g_deg[N_NODES];                       // degree per src
__device__ int    g_ei_is_i64;

// ---------------- helpers ----------------------------------------------------
__device__ __forceinline__ uint32_t smem_u32(const void* p) {
    uint32_t a;
    asm("{ .reg .u64 t; cvta.to.shared.u64 t, %1; cvt.u32.u64 %0, t; }" : "=r"(a) : "l"(p));
    return a;
}

#define LDSM_X4(r, addr)                                                        \
    asm volatile("ldmatrix.sync.aligned.m8n8.x4.shared.b16 {%0,%1,%2,%3}, [%4];"\
                 : "=r"((r)[0]), "=r"((r)[1]), "=r"((r)[2]), "=r"((r)[3])       \
                 : "r"(addr))
#define MMA_FP16(c, a, b0, b1)                                                  \
    asm volatile("mma.sync.aligned.m16n8k16.row.col.f32.f16.f16.f32 "           \
                 "{%0,%1,%2,%3}, {%4,%5,%6,%7}, {%8,%9}, {%0,%1,%2,%3};"        \
                 : "+f"((c)[0]), "+f"((c)[1]), "+f"((c)[2]), "+f"((c)[3])       \
                 : "r"((a)[0]), "r"((a)[1]), "r"((a)[2]), "r"((a)[3]),          \
                   "r"(b0), "r"(b1))

// Split (a,b) -> fp16 hi pair + fp16 residual pair; store packed u32.
__device__ __forceinline__ void store_pair(char* hi_t, char* lo_t, int row, int col,
                                           float a, float b) {
    const uint32_t off = (uint32_t)row * ASTRIDE + (uint32_t)col * 2;
    __half2 h = __floats2half2_rn(a, b);
    float ra = a - __half2float(__low2half(h));
    float rb = b - __half2float(__high2half(h));
    __half2 l = __floats2half2_rn(ra, rb);
    *(uint32_t*)(hi_t + off) = *(uint32_t*)&h;
    *(uint32_t*)(lo_t + off) = *(uint32_t*)&l;
}
// fp16 round only (for B tile: weights)
__device__ __forceinline__ void store_b(char* hi_t, int row, int col, float a, float b) {
    const uint32_t off = (uint32_t)row * ASTRIDE + (uint32_t)col * 2;
    __half2 h = __floats2half2_rn(a, b);
    *(uint32_t*)(hi_t + off) = *(uint32_t*)&h;
}

// ---------------- small kernels ---------------------------------------------
__global__ void detect_ei_kernel(const unsigned* __restrict__ p32) {
    __shared__ unsigned red[256];
    unsigned acc = 0;
    for (int i = threadIdx.x; i < 1024; i += 256) {
        acc |= p32[2 * i + 1];
        acc |= p32[2 * (N_EDGES / 2 + i) + 1];
    }
    red[threadIdx.x] = acc;
    __syncthreads();
    for (int s = 128; s > 0; s >>= 1) {
        if (threadIdx.x < s) red[threadIdx.x] |= red[threadIdx.x + s];
        __syncthreads();
    }
    if (threadIdx.x == 0) g_ei_is_i64 = (red[0] == 0) ? 1 : 0;
}

__global__ void zero_kernel() {
    int i = blockIdx.x * blockDim.x + threadIdx.x;
    if (i < N_NODES * (DIM / 4)) g_aggX[i] = make_float4(0.f, 0.f, 0.f, 0.f);
    if (i < N_NODES) g_deg[i] = 0.f;
}

// scatter: aggX[src] += X[dst]; deg[src] += 1. One warp per edge.
__global__ void scatter_kernel(const void* __restrict__ ei_raw,
                               const float* __restrict__ X) {
    const int e = blockIdx.x * (blockDim.x >> 5) + (threadIdx.x >> 5);
    if (e >= N_EDGES) return;
    const int lane = threadIdx.x & 31;

    unsigned src, dst;
    if (g_ei_is_i64) {
        const long long* p = (const long long*)ei_raw;
        src = (unsigned)p[e];
        dst = (unsigned)p[N_EDGES + e];
    } else {
        const int* p = (const int*)ei_raw;
        src = (unsigned)p[e];
        dst = (unsigned)p[N_EDGES + e];
    }
    if (src >= N_NODES || dst >= N_NODES) return;

    const float4 v = __ldg(reinterpret_cast<const float4*>(X) + (size_t)dst * (DIM / 4) + lane);
    float4* a = &g_aggX[(size_t)src * (DIM / 4) + lane];
    asm volatile("red.global.add.v4.f32 [%0], {%1, %2, %3, %4};"
                 :: "l"(a), "f"(v.x), "f"(v.y), "f"(v.z), "f"(v.w) : "memory");
    if (lane == 0)
        asm volatile("red.global.add.f32 [%0], %1;" :: "l"(&g_deg[src]), "f"(1.0f) : "memory");
}

// ---------------- fused double-GEMM (mma.sync fp16 hi/lo split, 2 passes) ----
// 512 threads = 16 warps. Warp w: row strip s=w>>1 (rows 16s..16s+15),
// column half h=w&1 (cols 64h..64h+63). acc[8][4] = 32 regs.
//   y   = msg_W . aggX[row] + deg[row]*msg_b + (1+eps)*X[row]
//   out = relu(lin_W . y + lin_b)
// Each GEMM = Ahi.B + Alo.B (B fp16-rounded; error ~2^-12, well under 1e-3).

__device__ __forceinline__ void fill_B(char* smem, const float* __restrict__ w,
                                       int tid) {
    const int row = tid >> 2;                  // weight row g = output col n
    const int c0  = (tid & 3) * 32;
    const float2* wr = (const float2*)(w + (size_t)row * DIM + c0);
    #pragma unroll 8
    for (int c = 0; c < 32; c += 2) {
        float2 v = __ldg(wr + c / 2);
        store_b(smem + SM_BHI, row, c0 + c, v.x, v.y);
    }
}

__device__ __forceinline__ void do_gemm(uint32_t sb, int s, int h, int t,
                                        float (*acc)[4]) {
    #pragma unroll 1
    for (int k = 0; k < 8; k++) {
        const uint32_t a_addr = sb + SM_AHI + (uint32_t)(s * 16 + (t & 15)) * ASTRIDE
                              + (uint32_t)k * 32 + (uint32_t)(t >> 4) * 16;
        uint32_t ah[4], al[4];
        LDSM_X4(ah, a_addr);
        LDSM_X4(al, a_addr + TILE_BYTES);
        #pragma unroll
        for (int jp = 0; jp < 4; jp++) {
            // X4 loads B for two adjacent j tiles: j0 = h*8+jp*2, j1 = j0+1
            const uint32_t b_addr = sb + SM_BHI
                + (uint32_t)((h * 8 + jp * 2) * 8 + (t >> 4) * 8 + (t & 7)) * ASTRIDE
                + (uint32_t)k * 32 + (uint32_t)((t >> 3) & 1) * 16;
            uint32_t bb[4];
            LDSM_X4(bb, b_addr);
            MMA_FP16(acc[jp * 2 + 0], ah, bb[0], bb[1]);
            MMA_FP16(acc[jp * 2 + 0], al, bb[0], bb[1]);
            MMA_FP16(acc[jp * 2 + 1], ah, bb[2], bb[3]);
            MMA_FP16(acc[jp * 2 + 1], al, bb[2], bb[3]);
        }
    }
}

__global__ void __launch_bounds__(512, 1)
fused_kernel(const float* __restrict__ X,
             const float* __restrict__ msg_w, const float* __restrict__ msg_b,
             const float* __restrict__ lin_w, const float* __restrict__ lin_b,
             const float* __restrict__ eps_ptr, float* __restrict__ out) {
    extern __shared__ char smem[];
    const uint32_t sb = smem_u32(smem);
    const int tid = threadIdx.x;
    const int w = tid >> 5, t = tid & 31;
    const int s = w >> 1, h = w & 1;
    const int g = t >> 2, tig = t & 3;
    const int base = blockIdx.x * TILE_M;

    // ---- fill A (aggX hi/lo) and B (msg_w) ----
    {
        const int row = tid >> 2;
        const int c0 = (tid & 3) * 32;
        const int grow = base + row;
        const bool v = (grow < N_NODES);
        const float2* ar = (const float2*)((const float*)g_aggX + (size_t)grow * DIM + c0);
        #pragma unroll 8
        for (int c = 0; c < 32; c += 2) {
            float2 a = v ? __ldg(ar + c / 2) : make_float2(0.f, 0.f);
            store_pair(smem + SM_AHI, smem + SM_ALO, row, c0 + c, a.x, a.y);
        }
        fill_B(smem, msg_w, tid);
    }
    __syncthreads();

    float acc[8][4];
    #pragma unroll
    for (int j = 0; j < 8; j++)
        #pragma unroll
        for (int i = 0; i < 4; i++) acc[j][i] = 0.f;

    // ---- GEMM 1: acc = msg_W . aggX ----
    do_gemm(sb, s, h, t, acc);
    __syncthreads();   // warp pair shares A rows: all reads done before rewrite

    // ---- epilogue 1: y = acc + deg*msg_b + (1+eps)X -> back into A tiles ----
    const float epsv = 1.0f + __ldg(eps_ptr);
    const int r0 = s * 16 + g, r1 = r0 + 8;
    const int gr0 = base + r0, gr1 = base + r1;
    const bool v0 = (gr0 < N_NODES), v1 = (gr1 < N_NODES);
    const float d0 = v0 ? __ldg(&g_deg[gr0]) : 0.f;
    const float d1 = v1 ? __ldg(&g_deg[gr1]) : 0.f;
    #pragma unroll
    for (int j = 0; j < 8; j++) {
        const int col = h * 64 + j * 8 + 2 * tig;
        float2 mb = __ldg((const float2*)(msg_b + col));
        float2 x0 = v0 ? __ldg((const float2*)(X + (size_t)gr0 * DIM + col)) : make_float2(0.f, 0.f);
        float2 x1 = v1 ? __ldg((const float2*)(X + (size_t)gr1 * DIM + col)) : make_float2(0.f, 0.f);
        float y00 = acc[j][0] + d0 * mb.x + epsv * x0.x;
        float y01 = acc[j][1] + d0 * mb.y + epsv * x0.y;
        float y10 = acc[j][2] + d1 * mb.x + epsv * x1.x;
        float y11 = acc[j][3] + d1 * mb.y + epsv * x1.y;
        store_pair(smem + SM_AHI, smem + SM_ALO, r0, col, y00, y01);
        store_pair(smem + SM_AHI, smem + SM_ALO, r1, col, y10, y11);
        acc[j][0] = acc[j][1] = acc[j][2] = acc[j][3] = 0.f;
    }
    fill_B(smem, lin_w, tid);   // B reads of gemm1 all completed at last sync
    __syncthreads();

    // ---- GEMM 2: acc = lin_W . y ----
    do_gemm(sb, s, h, t, acc);

    // ---- epilogue 2: out = relu(acc + lin_b) ----
    #pragma unroll
    for (int j = 0; j < 8; j++) {
        const int col = h * 64 + j * 8 + 2 * tig;
        float2 lb = __ldg((const float2*)(lin_b + col));
        if (v0) {
            float2 o;
            o.x = fmaxf(acc[j][0] + lb.x, 0.f);
            o.y = fmaxf(acc[j][1] + lb.y, 0.f);
            *(float2*)(out + (size_t)gr0 * DIM + col) = o;
        }
        if (v1) {
            float2 o;
            o.x = fmaxf(acc[j][2] + lb.x, 0.f);
            o.y = fmaxf(acc[j][3] + lb.y, 0.f);
            *(float2*)(out + (size_t)gr1 * DIM + col) = o;
        }
    }
}

// ---------------- launch ----------------------------------------------------
extern "C" void kernel_launch(void* const* d_in, const int* in_sizes, int n_in,
                              void* d_out, int out_size) {
    const float* X   = nullptr;
    const void*  ei  = nullptr;
    const float* eps = nullptr;
    const float* w[2] = {nullptr, nullptr};   // [msg_w, lin_w]
    const float* b[2] = {nullptr, nullptr};   // [msg_b, lin_b]
    int wi = 0, bi = 0;
    for (int i = 0; i < n_in; i++) {
        const int s = in_sizes[i];
        if      (s == N_NODES * DIM) X   = (const float*)d_in[i];
        else if (s == 2 * N_EDGES)   ei  = d_in[i];
        else if (s == 1)             eps = (const float*)d_in[i];
        else if (s == DIM * DIM)   { if (wi < 2) w[wi++] = (const float*)d_in[i]; }
        else if (s == DIM)         { if (bi < 2) b[bi++] = (const float*)d_in[i]; }
    }
    float* out = (float*)d_out;

    cudaFuncSetAttribute(fused_kernel, cudaFuncAttributeMaxDynamicSharedMemorySize, SM_TOTAL);

    const int zero_blocks = (N_NODES * (DIM / 4) + 255) / 256;   // 6250
    const int scat_blocks = (N_EDGES + 7) / 8;                   // 78125

    detect_ei_kernel<<<1, 256>>>((const unsigned*)ei);
    zero_kernel<<<zero_blocks, 256>>>();
    scatter_kernel<<<scat_blocks, 256>>>(ei, X);
    fused_kernel<<<NTILES, 512, SM_TOTAL>>>(X, w[0], b[0], w[1], b[1], eps, out);
}